// round 5
// baseline (speedup 1.0000x reference)
#include <cuda_runtime.h>
#include <cstddef>
#include <cstdint>

// HardDTW max-plus scan — 4-CTA cluster K-split, 8-level skewed wavefront,
// CHUNK=32, register-resident boundary vector (no broadcast shfl).
//
//   out[b,0,k] = x[b,0,k]
//   out[b,t,k] = x[b,t,k] + max(out[b,t-1,k], out[b,t-1,k-1])   (k-1 < 0 -> -inf)
//
// Grid = B*4 CTAs; cluster of 4 covers one batch, rank r owns columns
// [r*256, (r+1)*256). 64 threads/CTA (2 warps), thread carries one float4.
// Pipeline level = rank*2 + warp (8 levels), skewed CHUNK steps per level.
// Warp0->warp1 edges via local smem; CTA r warp1 -> CTA r+1 warp0 via DSMEM
// (st.shared::cluster through mapa). One cluster.sync per epoch orders all
// edge traffic. Consumers bulk-load the 32 boundary floats into registers
// at epoch start; per-step selection is compile-time under full unroll.

namespace {
constexpr int T = 2048;
constexpr int K = 1024;
constexpr int NSPLIT = 4;
constexpr int KSUB = K / NSPLIT;             // 256
constexpr int THREADS = KSUB / 4;            // 64
constexpr int NWARP = THREADS / 32;          // 2
constexpr int LEVELS = NSPLIT * NWARP;       // 8
constexpr int RS = K / 4;                    // float4 per full row
constexpr int CHUNK = 32;
constexpr int NCHUNK = T / CHUNK;            // 64
constexpr int NEPOCH = NCHUNK + LEVELS - 1;  // 71
constexpr int D = 16;                        // rolling x prefetch depth
}

__device__ __forceinline__ float bsel(const float4* q, int j) {
    const float4 v = q[j >> 2];
    switch (j & 3) {
        case 0: return v.x;
        case 1: return v.y;
        case 2: return v.z;
        default: return v.w;
    }
}

__global__ __launch_bounds__(THREADS, 1) __cluster_dims__(NSPLIT, 1, 1)
void harddtw_cluster32_kernel(const float* __restrict__ x,
                              float* __restrict__ out) {
    __shared__ __align__(16) float wedges[2][CHUNK];  // warp0 -> warp1
    __shared__ __align__(16) float cedges[2][CHUNK];  // prev CTA -> our warp0

    const int tid   = threadIdx.x;
    const int lane  = tid & 31;
    const int warp  = tid >> 5;
    const int rank  = blockIdx.x & (NSPLIT - 1);
    const int batch = blockIdx.x >> 2;
    const int level = rank * NWARP + warp;
    const float NEG_INF = __int_as_float(0xff800000);

    const float4* __restrict__ xr =
        reinterpret_cast<const float4*>(x + (size_t)batch * T * K)
        + rank * (KSUB / 4) + tid;
    float4* __restrict__ orow =
        reinterpret_cast<float4*>(out + (size_t)batch * T * K)
        + rank * (KSUB / 4) + tid;

    // DSMEM address of cedges in the next-rank CTA.
    uint32_t ced_local = (uint32_t)__cvta_generic_to_shared(&cedges[0][0]);
    uint32_t ced_remote;
    {
        int tgt = (rank + 1 < NSPLIT) ? (rank + 1) : rank;  // self-map for last rank
        asm("mapa.shared::cluster.u32 %0, %1, %2;"
            : "=r"(ced_remote) : "r"(ced_local), "r"(tgt));
    }

    const bool wprod = (warp == 0) && (lane == 31);
    const bool cprod = (warp == NWARP - 1) && (lane == 31) && (rank < NSPLIT - 1);

    // Rolling x prefetch queue, depth D (< CHUNK): slot j&15 holds row t.
    float4 xq[D];
#pragma unroll
    for (int j = 0; j < D; ++j) xq[j] = xr[(size_t)j * RS];

    float4 cur = make_float4(NEG_INF, NEG_INF, NEG_INF, NEG_INF);

    for (int e = 0; e < NEPOCH; ++e) {
        const int c = e - level;
        if (0 <= c && c < NCHUNK) {
            const int t0 = c * CHUNK;
            const int rbuf = (e - 1) & 1;

            // Bulk-load upstream boundary vector into registers (broadcast LDS).
            float4 bvq[CHUNK / 4];
            {
                const float4* src = reinterpret_cast<const float4*>(
                    (warp == 0) ? cedges[rbuf] : wedges[rbuf]);
#pragma unroll
                for (int i = 0; i < CHUNK / 4; ++i) bvq[i] = src[i];
            }

            // Publish slot 0: carry entering this chunk (garbage if c==0, unused).
            if (wprod) wedges[e & 1][0] = cur.w;
            if (cprod) {
                uint32_t a = ced_remote + (uint32_t)((e & 1) * CHUNK * 4);
                asm volatile("st.shared::cluster.f32 [%0], %1;"
                             :: "r"(a), "f"(cur.w) : "memory");
            }

#pragma unroll
            for (int j = 0; j < CHUNK; ++j) {
                const int t = t0 + j;
                const float4 xv = xq[j & (D - 1)];
                if (t + D < T) xq[j & (D - 1)] = xr[(size_t)(t + D) * RS];

                if (c == 0 && j == 0) {
                    cur = xv;  // init row: out[0] = x[0]
                } else {
                    float up = __shfl_up_sync(0xffffffffu, cur.w, 1);
                    if (lane == 0)
                        up = (level == 0) ? NEG_INF : bsel(bvq, j);

                    float4 n;
                    n.x = xv.x + fmaxf(cur.x, up);
                    n.y = xv.y + fmaxf(cur.y, cur.x);
                    n.z = xv.z + fmaxf(cur.z, cur.y);
                    n.w = xv.w + fmaxf(cur.w, cur.z);
                    cur = n;
                }

                orow[(size_t)t * RS] = cur;

                if (j < CHUNK - 1) {
                    if (wprod) wedges[e & 1][j + 1] = cur.w;
                    if (cprod) {
                        uint32_t a = ced_remote +
                            (uint32_t)(((e & 1) * CHUNK + j + 1) * 4);
                        asm volatile("st.shared::cluster.f32 [%0], %1;"
                                     :: "r"(a), "f"(cur.w) : "memory");
                    }
                }
            }
        }

        // Cluster-wide barrier: orders smem + DSMEM edge writes for next epoch.
        asm volatile("barrier.cluster.arrive.aligned;" ::: "memory");
        asm volatile("barrier.cluster.wait.aligned;" ::: "memory");
    }
}

extern "C" void kernel_launch(void* const* d_in, const int* in_sizes, int n_in,
                              void* d_out, int out_size) {
    const float* x = (const float*)d_in[0];
    float* out = (float*)d_out;
    const int B = in_sizes[0] / (T * K);
    harddtw_cluster32_kernel<<<B * NSPLIT, THREADS>>>(x, out);
}

// round 6
// speedup vs baseline: 1.0465x; 1.0465x over previous
#include <cuda_runtime.h>
#include <cstddef>
#include <cstdint>

// HardDTW max-plus scan — 2-CTA-per-batch K-split, 16-level skewed wavefront.
//
//   out[b,0,k] = x[b,0,k]
//   out[b,t,k] = x[b,t,k] + max(out[b,t-1,k], out[b,t-1,k-1])   (k-1 < 0 -> -inf)
//
// Grid = B*2 CTAs. CTA (2b+h) owns columns [h*512, h*512+512) of batch b.
// 256 threads (8 warps, 2 per SMSP), thread carries one float2.
// Pipeline levels: CTA0 warp w -> level w; CTA1 warp w -> level 9+w (the +1
// gives a 2-epoch margin on the cross-CTA handoff so the consumer poll is
// satisfied on arrival). CHUNK=16 steps per level per epoch; one
// __syncthreads per epoch inside each CTA.
// Intra-CTA edges via double-buffered smem; cross-CTA edge (k=511 -> 512) via
// a full-size gmem buffer (128 chunks x 16 floats per batch, never reused
// within a launch) + monotonic flag with release/acquire. Flags are zeroed by
// an init kernel launched first in the same stream (graph-ordered).

namespace {
constexpr int T = 2048;
constexpr int K = 1024;
constexpr int MAXB = 32;
constexpr int THREADS = 256;
constexpr int NWARP = 8;
constexpr int CHUNK = 16;
constexpr int NCHUNK = T / CHUNK;                 // 128
constexpr int CROSS = 9;                          // level offset of CTA1 warp0
constexpr int NEPOCH = NCHUNK + CROSS + NWARP - 1;  // 144
constexpr int D = 16;                             // x prefetch depth (== CHUNK)
constexpr int RS2 = K / 2;                        // float2 per full row = 512
}

__device__ float eg_edges[MAXB][NCHUNK][CHUNK];   // cross-CTA edge values
__device__ int   eg_flag[MAXB][32];               // [b][0], padded to 128B

__global__ void harddtw_init_kernel() {
    if (threadIdx.x < MAXB) eg_flag[threadIdx.x][0] = 0;
}

__device__ __forceinline__ float bsel(const float4* q, int j) {
    const float4 v = q[j >> 2];
    switch (j & 3) {
        case 0: return v.x;
        case 1: return v.y;
        case 2: return v.z;
        default: return v.w;
    }
}

__global__ __launch_bounds__(THREADS, 1)
void harddtw_split2_kernel(const float* __restrict__ x,
                           float* __restrict__ out) {
    __shared__ __align__(16) float edges[2][NWARP][CHUNK];

    const int tid  = threadIdx.x;
    const int lane = tid & 31;
    const int warp = tid >> 5;
    const int half = blockIdx.x & 1;
    const int b    = blockIdx.x >> 1;
    const int level = half ? (CROSS + warp) : warp;
    const float NEG_INF = __int_as_float(0xff800000);

    const float2* __restrict__ xr =
        reinterpret_cast<const float2*>(x + (size_t)b * T * K)
        + half * (RS2 / 2) + tid;
    float2* __restrict__ orow =
        reinterpret_cast<float2*>(out + (size_t)b * T * K)
        + half * (RS2 / 2) + tid;

    const bool sprod = (warp < NWARP - 1) && (lane == 31);      // smem edges
    const bool gprod = (half == 0) && (warp == NWARP - 1) && (lane == 31);
    const bool gcons = (half == 1) && (warp == 0);
    const int pw = (warp == 0) ? 0 : (warp - 1);

    int* const flagp = &eg_flag[b][0];

    // Rolling x prefetch: slot j holds row t0+j's value (depth D == CHUNK).
    float2 xq[D];
#pragma unroll
    for (int j = 0; j < D; ++j) xq[j] = xr[(size_t)j * RS2];

    float2 cur;
    cur.x = NEG_INF; cur.y = NEG_INF;

    for (int e = 0; e < NEPOCH; ++e) {
        const int c = e - level;
        if (0 <= c && c < NCHUNK) {
            const int t0 = c * CHUNK;

            // ── Fetch upstream boundary vector into registers ──
            float4 bvq[CHUNK / 4];
            if (gcons) {
                // Wait for producer CTA to have published chunk c (2-epoch margin).
                int f;
                do {
                    asm volatile("ld.acquire.gpu.global.s32 %0, [%1];"
                                 : "=r"(f) : "l"(flagp) : "memory");
                } while (f < c + 1);
                const float4* src =
                    reinterpret_cast<const float4*>(&eg_edges[b][c][0]);
#pragma unroll
                for (int i = 0; i < CHUNK / 4; ++i) bvq[i] = __ldcg(src + i);
            } else {
                const float4* src =
                    reinterpret_cast<const float4*>(&edges[(e - 1) & 1][pw][0]);
#pragma unroll
                for (int i = 0; i < CHUNK / 4; ++i) bvq[i] = src[i];
            }

            // Publish slot 0: carry entering this chunk (garbage at c==0, unused).
            if (sprod) edges[e & 1][warp][0] = cur.y;
            if (gprod) eg_edges[b][c][0] = cur.y;

#pragma unroll
            for (int j = 0; j < CHUNK; ++j) {
                const int t = t0 + j;
                const float2 xv = xq[j];
                if (t + D < T) xq[j] = xr[(size_t)(t + D) * RS2];

                if (c == 0 && j == 0) {
                    cur = xv;  // init row: out[0] = x[0]
                } else {
                    float up = __shfl_up_sync(0xffffffffu, cur.y, 1);
                    if (lane == 0)
                        up = (level == 0) ? NEG_INF : bsel(bvq, j);
                    float2 n;
                    n.x = xv.x + fmaxf(cur.x, up);
                    n.y = xv.y + fmaxf(cur.y, cur.x);
                    cur = n;
                }

                orow[(size_t)t * RS2] = cur;

                if (j < CHUNK - 1) {
                    if (sprod) edges[e & 1][warp][j + 1] = cur.y;
                    if (gprod) eg_edges[b][c][j + 1] = cur.y;
                }
            }

            // Release this chunk's gmem edges to the consumer CTA.
            if (gprod) {
                int v = c + 1;
                asm volatile("st.release.gpu.global.s32 [%0], %1;"
                             :: "l"(flagp), "r"(v) : "memory");
            }
        }
        __syncthreads();
    }
}

extern "C" void kernel_launch(void* const* d_in, const int* in_sizes, int n_in,
                              void* d_out, int out_size) {
    const float* x = (const float*)d_in[0];
    float* out = (float*)d_out;
    const int B = in_sizes[0] / (T * K);
    harddtw_init_kernel<<<1, 32>>>();
    harddtw_split2_kernel<<<B * 2, THREADS>>>(x, out);
}